// round 11
// baseline (speedup 1.0000x reference)
#include <cuda_runtime.h>

#define EMBED 16
// tokens = 128 * 8192 = 1048576; block handles 512 tokens (2 per thread)

// History:
//   R8:  const-port weights, 256 FFMA -> 33.8us (issue-bound 70%).
//   R9:  weights via LDG -> 59.4us REGRESSION (LDG->LDG floor 4 on LSU path).
//   R10: const-port + FFMA2 -> 31.5us (kernel 27.4); binding = const port:
//        64 LDC.128/token at LDC->LDC floor 8 ~= 14.7us.
//   R11: 2 tokens/thread -> weight LDC amortized across both tokens
//        (32 LDC.128/token -> ~7.4us const-port time). Block-strided token
//        pair keeps both streams dense. Cap (256,2)=128 regs (live ~95).

// c_wp2[e*4 + k] = { pack(w[4k][e], w[4k+1][e]), pack(w[4k+2][e], w[4k+3][e]) }
__constant__ ulonglong2 c_wp2[EMBED * 4];
__device__ unsigned long long g_stage[EMBED * 8];

__global__ void prep_kernel(const float* __restrict__ w_out)
{
    int t = threadIdx.x;                  // 128 threads: t = e*8 + j
    if (t < EMBED * 8) {
        int e = t >> 3;
        int j = t & 7;                    // output pair (2j, 2j+1)
        float lo = w_out[(2 * j)     * EMBED + e];
        float hi = w_out[(2 * j + 1) * EMBED + e];
        unsigned long long p;
        asm("mov.b64 %0, {%1, %2};" : "=l"(p) : "f"(lo), "f"(hi));
        g_stage[t] = p;
    }
}

__global__ __launch_bounds__(256, 2)
void mhaq_kernel(const float* __restrict__ x,
                 const float* __restrict__ theta,
                 float* __restrict__ y)
{
    int tokA = blockIdx.x * 512 + threadIdx.x;        // dense warp stream A
    int tokB = tokA + 256;                            // dense warp stream B

    const float4* xa = reinterpret_cast<const float4*>(x) + (size_t)tokA * 4;
    const float4* xb = reinterpret_cast<const float4*>(x) + (size_t)tokB * 4;
    float* ya = y + (size_t)tokA * EMBED;
    float* yb = y + (size_t)tokB * EMBED;

    // 8 independent 128-bit loads -> MLP=8
    float4 a0 = xa[0], a1 = xa[1], a2 = xa[2], a3 = xa[3];
    float4 b0 = xb[0], b1 = xb[1], b2 = xb[2], b3 = xb[3];

    const float4* tv = reinterpret_cast<const float4*>(theta);
    float4 t0 = tv[0], t1 = tv[1], t2 = tv[2], t3 = tv[3];

    float phA[EMBED] = {
        a0.x + t0.x, a0.y + t0.y, a0.z + t0.z, a0.w + t0.w,
        a1.x + t1.x, a1.y + t1.y, a1.z + t1.z, a1.w + t1.w,
        a2.x + t2.x, a2.y + t2.y, a2.z + t2.z, a2.w + t2.w,
        a3.x + t3.x, a3.y + t3.y, a3.z + t3.z, a3.w + t3.w };
    float phB[EMBED] = {
        b0.x + t0.x, b0.y + t0.y, b0.z + t0.z, b0.w + t0.w,
        b1.x + t1.x, b1.y + t1.y, b1.z + t1.z, b1.w + t1.w,
        b2.x + t2.x, b2.y + t2.y, b2.z + t2.z, b2.w + t2.w,
        b3.x + t3.x, b3.y + t3.y, b3.z + t3.z, b3.w + t3.w };

    unsigned long long accA[8], accB[8];

    // e = 0: init; ONE set of 4 LDC.128 feeds both tokens
    {
        float zA = __cosf(phA[0]);
        float zB = __cosf(phB[0]);
        unsigned long long zA2, zB2;
        asm("mov.b64 %0, {%1, %1};" : "=l"(zA2) : "f"(zA));
        asm("mov.b64 %0, {%1, %1};" : "=l"(zB2) : "f"(zB));
        ulonglong2 p0 = c_wp2[0], p1 = c_wp2[1], p2 = c_wp2[2], p3 = c_wp2[3];
        asm("mul.rn.f32x2 %0, %1, %2;" : "=l"(accA[0]) : "l"(zA2), "l"(p0.x));
        asm("mul.rn.f32x2 %0, %1, %2;" : "=l"(accA[1]) : "l"(zA2), "l"(p0.y));
        asm("mul.rn.f32x2 %0, %1, %2;" : "=l"(accA[2]) : "l"(zA2), "l"(p1.x));
        asm("mul.rn.f32x2 %0, %1, %2;" : "=l"(accA[3]) : "l"(zA2), "l"(p1.y));
        asm("mul.rn.f32x2 %0, %1, %2;" : "=l"(accA[4]) : "l"(zA2), "l"(p2.x));
        asm("mul.rn.f32x2 %0, %1, %2;" : "=l"(accA[5]) : "l"(zA2), "l"(p2.y));
        asm("mul.rn.f32x2 %0, %1, %2;" : "=l"(accA[6]) : "l"(zA2), "l"(p3.x));
        asm("mul.rn.f32x2 %0, %1, %2;" : "=l"(accA[7]) : "l"(zA2), "l"(p3.y));
        asm("mul.rn.f32x2 %0, %1, %2;" : "=l"(accB[0]) : "l"(zB2), "l"(p0.x));
        asm("mul.rn.f32x2 %0, %1, %2;" : "=l"(accB[1]) : "l"(zB2), "l"(p0.y));
        asm("mul.rn.f32x2 %0, %1, %2;" : "=l"(accB[2]) : "l"(zB2), "l"(p1.x));
        asm("mul.rn.f32x2 %0, %1, %2;" : "=l"(accB[3]) : "l"(zB2), "l"(p1.y));
        asm("mul.rn.f32x2 %0, %1, %2;" : "=l"(accB[4]) : "l"(zB2), "l"(p2.x));
        asm("mul.rn.f32x2 %0, %1, %2;" : "=l"(accB[5]) : "l"(zB2), "l"(p2.y));
        asm("mul.rn.f32x2 %0, %1, %2;" : "=l"(accB[6]) : "l"(zB2), "l"(p3.x));
        asm("mul.rn.f32x2 %0, %1, %2;" : "=l"(accB[7]) : "l"(zB2), "l"(p3.y));
    }

    // e = 1..15: 2 MUFU + 2 packs + 4 LDC.128 + 16 FFMA2 (both tokens)
    #pragma unroll
    for (int e = 1; e < EMBED; e++) {
        float zA = __cosf(phA[e]);
        float zB = __cosf(phB[e]);
        unsigned long long zA2, zB2;
        asm("mov.b64 %0, {%1, %1};" : "=l"(zA2) : "f"(zA));
        asm("mov.b64 %0, {%1, %1};" : "=l"(zB2) : "f"(zB));
        ulonglong2 p0 = c_wp2[e * 4 + 0];
        ulonglong2 p1 = c_wp2[e * 4 + 1];
        ulonglong2 p2 = c_wp2[e * 4 + 2];
        ulonglong2 p3 = c_wp2[e * 4 + 3];
        asm("fma.rn.f32x2 %0, %1, %2, %0;" : "+l"(accA[0]) : "l"(zA2), "l"(p0.x));
        asm("fma.rn.f32x2 %0, %1, %2, %0;" : "+l"(accA[1]) : "l"(zA2), "l"(p0.y));
        asm("fma.rn.f32x2 %0, %1, %2, %0;" : "+l"(accA[2]) : "l"(zA2), "l"(p1.x));
        asm("fma.rn.f32x2 %0, %1, %2, %0;" : "+l"(accA[3]) : "l"(zA2), "l"(p1.y));
        asm("fma.rn.f32x2 %0, %1, %2, %0;" : "+l"(accA[4]) : "l"(zA2), "l"(p2.x));
        asm("fma.rn.f32x2 %0, %1, %2, %0;" : "+l"(accA[5]) : "l"(zA2), "l"(p2.y));
        asm("fma.rn.f32x2 %0, %1, %2, %0;" : "+l"(accA[6]) : "l"(zA2), "l"(p3.x));
        asm("fma.rn.f32x2 %0, %1, %2, %0;" : "+l"(accA[7]) : "l"(zA2), "l"(p3.y));
        asm("fma.rn.f32x2 %0, %1, %2, %0;" : "+l"(accB[0]) : "l"(zB2), "l"(p0.x));
        asm("fma.rn.f32x2 %0, %1, %2, %0;" : "+l"(accB[1]) : "l"(zB2), "l"(p0.y));
        asm("fma.rn.f32x2 %0, %1, %2, %0;" : "+l"(accB[2]) : "l"(zB2), "l"(p1.x));
        asm("fma.rn.f32x2 %0, %1, %2, %0;" : "+l"(accB[3]) : "l"(zB2), "l"(p1.y));
        asm("fma.rn.f32x2 %0, %1, %2, %0;" : "+l"(accB[4]) : "l"(zB2), "l"(p2.x));
        asm("fma.rn.f32x2 %0, %1, %2, %0;" : "+l"(accB[5]) : "l"(zB2), "l"(p2.y));
        asm("fma.rn.f32x2 %0, %1, %2, %0;" : "+l"(accB[6]) : "l"(zB2), "l"(p3.x));
        asm("fma.rn.f32x2 %0, %1, %2, %0;" : "+l"(accB[7]) : "l"(zB2), "l"(p3.y));
    }

    asm volatile("st.global.v2.b64 [%0], {%1, %2};" ::
                 "l"(ya + 0),  "l"(accA[0]), "l"(accA[1]) : "memory");
    asm volatile("st.global.v2.b64 [%0], {%1, %2};" ::
                 "l"(ya + 4),  "l"(accA[2]), "l"(accA[3]) : "memory");
    asm volatile("st.global.v2.b64 [%0], {%1, %2};" ::
                 "l"(ya + 8),  "l"(accA[4]), "l"(accA[5]) : "memory");
    asm volatile("st.global.v2.b64 [%0], {%1, %2};" ::
                 "l"(ya + 12), "l"(accA[6]), "l"(accA[7]) : "memory");
    asm volatile("st.global.v2.b64 [%0], {%1, %2};" ::
                 "l"(yb + 0),  "l"(accB[0]), "l"(accB[1]) : "memory");
    asm volatile("st.global.v2.b64 [%0], {%1, %2};" ::
                 "l"(yb + 4),  "l"(accB[2]), "l"(accB[3]) : "memory");
    asm volatile("st.global.v2.b64 [%0], {%1, %2};" ::
                 "l"(yb + 8),  "l"(accB[4]), "l"(accB[5]) : "memory");
    asm volatile("st.global.v2.b64 [%0], {%1, %2};" ::
                 "l"(yb + 12), "l"(accB[6]), "l"(accB[7]) : "memory");
}

extern "C" void kernel_launch(void* const* d_in, const int* in_sizes, int n_in,
                              void* d_out, int out_size)
{
    const float* x     = (const float*)d_in[0];   // [B, S, E]
    const float* theta = (const float*)d_in[1];   // [E]
    const float* w_out = (const float*)d_in[2];   // [E, E] row-major [o][e]
    float* y           = (float*)d_out;

    prep_kernel<<<1, 128>>>(w_out);

    void* stage_ptr = nullptr;
    cudaGetSymbolAddress(&stage_ptr, g_stage);
    cudaMemcpyToSymbolAsync(c_wp2, stage_ptr, EMBED * 8 * sizeof(unsigned long long),
                            0, cudaMemcpyDeviceToDevice, 0);

    int n_tokens = in_sizes[0] / EMBED;           // 1048576
    int blocks = n_tokens / 512;                  // 2048, exact (2 tokens/thread)
    mhaq_kernel<<<blocks, 256>>>(x, theta, y);
}

// round 12
// speedup vs baseline: 1.1179x; 1.1179x over previous
#include <cuda_runtime.h>

#define EMBED 16
// tokens = 128 * 8192 = 1048576 (divides 256 exactly)

// History:
//   R8:  const-port weights, 256 FFMA           -> 33.8us (issue 70%)
//   R9:  weights via LDG                        -> 59.4us (LSU LDG floor 4)
//   R10: const-port + FFMA2, (256,3), 47 regs   -> 31.5us total / 27.4 kernel
//        occ 52%, no unit saturated -> latency-exposure bound
//   R11: 2 tokens/thread, 78 regs, occ 31%      -> 34.9us REGRESSION
//        (traded warps for ILP; also falsified const-port-bound theory)
//   R12: R10 kernel + (256,5) cap=51 regs (R10 lived in 47 -> no spill risk)
//        -> occ up to 62.5%, better latency hiding.

// c_wp2[e*4 + k] = { pack(w[4k][e], w[4k+1][e]), pack(w[4k+2][e], w[4k+3][e]) }
__constant__ ulonglong2 c_wp2[EMBED * 4];
__device__ unsigned long long g_stage[EMBED * 8];

__global__ void prep_kernel(const float* __restrict__ w_out)
{
    int t = threadIdx.x;                  // 128 threads: t = e*8 + j
    if (t < EMBED * 8) {
        int e = t >> 3;
        int j = t & 7;                    // output pair (2j, 2j+1)
        float lo = w_out[(2 * j)     * EMBED + e];
        float hi = w_out[(2 * j + 1) * EMBED + e];
        unsigned long long p;
        asm("mov.b64 %0, {%1, %2};" : "=l"(p) : "f"(lo), "f"(hi));
        g_stage[t] = p;
    }
}

__global__ __launch_bounds__(256, 5)
void mhaq_kernel(const float* __restrict__ x,
                 const float* __restrict__ theta,
                 float* __restrict__ y)
{
    int token = blockIdx.x * blockDim.x + threadIdx.x;   // grid sized exactly

    const float4* xv = reinterpret_cast<const float4*>(x) + (size_t)token * 4;
    float*        yp = y + (size_t)token * EMBED;

    // 4 independent 128-bit loads -> MLP=4, coalesced 2048B/warp
    float4 a = xv[0];
    float4 b = xv[1];
    float4 c = xv[2];
    float4 d = xv[3];

    // theta: 4 warp-uniform LDG.128 (tiny, L1/L2-cached)
    const float4* tv = reinterpret_cast<const float4*>(theta);
    float4 t0 = tv[0], t1 = tv[1], t2 = tv[2], t3 = tv[3];

    float ph[EMBED] = {
        a.x + t0.x, a.y + t0.y, a.z + t0.z, a.w + t0.w,
        b.x + t1.x, b.y + t1.y, b.z + t1.z, b.w + t1.w,
        c.x + t2.x, c.y + t2.y, c.z + t2.z, c.w + t2.w,
        d.x + t3.x, d.y + t3.y, d.z + t3.z, d.w + t3.w };

    // packed accumulators: acc[j] lanes = outputs (2j, 2j+1)
    unsigned long long acc[8];

    // e = 0: mul.rn.f32x2 init; 4x LDC.128 (const port) per e
    {
        float z = __cosf(ph[0]);
        unsigned long long z2;
        asm("mov.b64 %0, {%1, %1};" : "=l"(z2) : "f"(z));
        ulonglong2 p0 = c_wp2[0], p1 = c_wp2[1], p2 = c_wp2[2], p3 = c_wp2[3];
        asm("mul.rn.f32x2 %0, %1, %2;" : "=l"(acc[0]) : "l"(z2), "l"(p0.x));
        asm("mul.rn.f32x2 %0, %1, %2;" : "=l"(acc[1]) : "l"(z2), "l"(p0.y));
        asm("mul.rn.f32x2 %0, %1, %2;" : "=l"(acc[2]) : "l"(z2), "l"(p1.x));
        asm("mul.rn.f32x2 %0, %1, %2;" : "=l"(acc[3]) : "l"(z2), "l"(p1.y));
        asm("mul.rn.f32x2 %0, %1, %2;" : "=l"(acc[4]) : "l"(z2), "l"(p2.x));
        asm("mul.rn.f32x2 %0, %1, %2;" : "=l"(acc[5]) : "l"(z2), "l"(p2.y));
        asm("mul.rn.f32x2 %0, %1, %2;" : "=l"(acc[6]) : "l"(z2), "l"(p3.x));
        asm("mul.rn.f32x2 %0, %1, %2;" : "=l"(acc[7]) : "l"(z2), "l"(p3.y));
    }

    // e = 1..15: 1 MUFU + 1 pack + 4 LDC.128 + 8 FFMA2 per e
    #pragma unroll
    for (int e = 1; e < EMBED; e++) {
        float z = __cosf(ph[e]);
        unsigned long long z2;
        asm("mov.b64 %0, {%1, %1};" : "=l"(z2) : "f"(z));
        ulonglong2 p0 = c_wp2[e * 4 + 0];
        ulonglong2 p1 = c_wp2[e * 4 + 1];
        ulonglong2 p2 = c_wp2[e * 4 + 2];
        ulonglong2 p3 = c_wp2[e * 4 + 3];
        asm("fma.rn.f32x2 %0, %1, %2, %0;" : "+l"(acc[0]) : "l"(z2), "l"(p0.x));
        asm("fma.rn.f32x2 %0, %1, %2, %0;" : "+l"(acc[1]) : "l"(z2), "l"(p0.y));
        asm("fma.rn.f32x2 %0, %1, %2, %0;" : "+l"(acc[2]) : "l"(z2), "l"(p1.x));
        asm("fma.rn.f32x2 %0, %1, %2, %0;" : "+l"(acc[3]) : "l"(z2), "l"(p1.y));
        asm("fma.rn.f32x2 %0, %1, %2, %0;" : "+l"(acc[4]) : "l"(z2), "l"(p2.x));
        asm("fma.rn.f32x2 %0, %1, %2, %0;" : "+l"(acc[5]) : "l"(z2), "l"(p2.y));
        asm("fma.rn.f32x2 %0, %1, %2, %0;" : "+l"(acc[6]) : "l"(z2), "l"(p3.x));
        asm("fma.rn.f32x2 %0, %1, %2, %0;" : "+l"(acc[7]) : "l"(z2), "l"(p3.y));
    }

    // acc[j] lanes are already (o=2j, o=2j+1): 4x STG.128
    asm volatile("st.global.v2.b64 [%0], {%1, %2};" ::
                 "l"(yp + 0), "l"(acc[0]), "l"(acc[1]) : "memory");
    asm volatile("st.global.v2.b64 [%0], {%1, %2};" ::
                 "l"(yp + 4), "l"(acc[2]), "l"(acc[3]) : "memory");
    asm volatile("st.global.v2.b64 [%0], {%1, %2};" ::
                 "l"(yp + 8), "l"(acc[4]), "l"(acc[5]) : "memory");
    asm volatile("st.global.v2.b64 [%0], {%1, %2};" ::
                 "l"(yp + 12), "l"(acc[6]), "l"(acc[7]) : "memory");
}

extern "C" void kernel_launch(void* const* d_in, const int* in_sizes, int n_in,
                              void* d_out, int out_size)
{
    const float* x     = (const float*)d_in[0];   // [B, S, E]
    const float* theta = (const float*)d_in[1];   // [E]
    const float* w_out = (const float*)d_in[2];   // [E, E] row-major [o][e]
    float* y           = (float*)d_out;

    // 1) pack pair-transposed weights into device staging (kernel launch)
    prep_kernel<<<1, 128>>>(w_out);

    // 2) ONE async D2D copy staging -> __constant__ (graph-capturable)
    void* stage_ptr = nullptr;
    cudaGetSymbolAddress(&stage_ptr, g_stage);    // host-side query, no stream op
    cudaMemcpyToSymbolAsync(c_wp2, stage_ptr, EMBED * 8 * sizeof(unsigned long long),
                            0, cudaMemcpyDeviceToDevice, 0);

    // 3) main kernel
    int n_tokens = in_sizes[0] / EMBED;           // 1048576, multiple of 256
    int threads = 256;
    int blocks = n_tokens / threads;              // 4096, exact
    mhaq_kernel<<<blocks, threads>>>(x, theta, y);
}